// round 6
// baseline (speedup 1.0000x reference)
#include <cuda_runtime.h>
#include <cuda_bf16.h>
#include <cstdint>

#define NN    8192
#define SDIM  2
#define JDIM  256
#define COUT  32

#define BM 128
#define BN 128
#define BK 32
#define KT 512          // SDIM*NN / BK
#define SK 40           // padded smem row stride in bf16 elems (80B, 16B-aligned)

// dynamic smem layout (bytes), per stage
#define ST_BYTES 40960
#define AHI_OFF  0
#define ALO_OFF  10240
#define BHI_OFF  20480
#define BLO_OFF  30720
#define SMEM_TOTAL (2 * ST_BYTES)

// Pre-split B operand: Yt[s][j][k] = Y[s][k][j], bf16 hi/lo (8.4 MB each)
__device__ __align__(256) __nv_bfloat16 g_Yt_hi[(size_t)SDIM * JDIM * NN];
__device__ __align__(256) __nv_bfloat16 g_Yt_lo[(size_t)SDIM * JDIM * NN];

// ---------------------------------------------------------------------------
// helpers
// ---------------------------------------------------------------------------
__device__ __forceinline__ uint32_t smem_u32(const void* p) {
    uint32_t a;
    asm("{ .reg .u64 t; cvta.to.shared.u64 t, %1; cvt.u32.u64 %0, t; }"
        : "=r"(a) : "l"(p));
    return a;
}

// pack two floats to bf16x2 (element0 = a, element1 = b)
__device__ __forceinline__ uint32_t bf2(float a, float b) {
    uint32_t r;
    asm("cvt.rn.bf16x2.f32 %0, %1, %2;" : "=r"(r) : "f"(b), "f"(a));
    return r;
}

__device__ __forceinline__ void ldsm4(uint32_t* r, uint32_t addr) {
    asm volatile("ldmatrix.sync.aligned.m8n8.x4.shared.b16 {%0,%1,%2,%3}, [%4];"
                 : "=r"(r[0]), "=r"(r[1]), "=r"(r[2]), "=r"(r[3]) : "r"(addr));
}

__device__ __forceinline__ void mma_bf16(float* c, const uint32_t* a, const uint32_t* b) {
    asm volatile(
        "mma.sync.aligned.m16n8k16.row.col.f32.bf16.bf16.f32 "
        "{%0,%1,%2,%3},{%4,%5,%6,%7},{%8,%9},{%0,%1,%2,%3};"
        : "+f"(c[0]), "+f"(c[1]), "+f"(c[2]), "+f"(c[3])
        : "r"(a[0]), "r"(a[1]), "r"(a[2]), "r"(a[3]), "r"(b[0]), "r"(b[1]));
}

// ---------------------------------------------------------------------------
// Kernel A: Yt_hi/lo[s][j][k] = split_bf16( sum_c x[b,k,c] * W[s,o,c] ),
//           j = b*32+o.  grid (64 kblocks, 8 b, 2 s), 256 threads.
// ---------------------------------------------------------------------------
__global__ void prep_Yt_kernel(const float* __restrict__ x,
                               const float* __restrict__ W) {
    __shared__ float Wsh[COUT][33];
    __shared__ __align__(16) float xsh[128][32];
    __shared__ __align__(16) __nv_bfloat16 yhi[COUT][128];
    __shared__ __align__(16) __nv_bfloat16 ylo[COUT][128];

    const int s  = blockIdx.z;
    const int b  = blockIdx.y;
    const int kb = blockIdx.x;
    const int t  = threadIdx.x;

    for (int i = t; i < 1024; i += 256) Wsh[i >> 5][i & 31] = W[s * 1024 + i];

    const float4* xbase = (const float4*)(x + ((size_t)b * NN + (size_t)kb * 128) * 32);
#pragma unroll
    for (int i = 0; i < 4; i++) {
        int f = t + 256 * i;
        ((float4*)&xsh[0][0])[f] = xbase[f];
    }
    __syncthreads();

    const int o = t & 31;
#pragma unroll
    for (int i = 0; i < 16; i++) {
        int ki = (t >> 5) + i * 8;
        float sum = 0.0f;
#pragma unroll
        for (int c = 0; c < 32; c++) sum += xsh[ki][c] * Wsh[o][c];
        __nv_bfloat16 h = __float2bfloat16(sum);
        float hf = __bfloat162float(h);
        __nv_bfloat16 l = __float2bfloat16(sum - hf);
        yhi[o][ki] = h;
        ylo[o][ki] = l;
    }
    __syncthreads();

    // writeback: each thread owns 16 elements = TWO uint4 (uint4 = 8 bf16)
    const int oo  = t >> 3;
    const int seg = t & 7;
    size_t base = ((size_t)(s * JDIM + b * 32 + oo)) * NN + (size_t)kb * 128 + seg * 16;
    *(uint4*)(&g_Yt_hi[base])     = *(const uint4*)(&yhi[oo][seg * 16]);
    *(uint4*)(&g_Yt_hi[base + 8]) = *(const uint4*)(&yhi[oo][seg * 16 + 8]);
    *(uint4*)(&g_Yt_lo[base])     = *(const uint4*)(&ylo[oo][seg * 16]);
    *(uint4*)(&g_Yt_lo[base + 8]) = *(const uint4*)(&ylo[oo][seg * 16 + 8]);
}

// ---------------------------------------------------------------------------
// Main GEMM via mma.sync bf16 (3-pass hi/lo split), double-buffered smem,
// depth-2 register staging, ONE __syncthreads per k-iteration.
// Grid: 128 CTAs = (64 m-tiles) x (2 j-halves). 256 threads = 8 warps (2x4).
// ---------------------------------------------------------------------------
__global__ __launch_bounds__(256, 1)
void graphconv_hmma_kernel(const float* __restrict__ supports,
                           const float* __restrict__ bias,
                           float* __restrict__ out) {
    extern __shared__ __align__(16) char smem[];
    const uint32_t sbase = smem_u32(smem);

    const int t     = threadIdx.x;
    const int wid   = t >> 5;
    const int lane  = t & 31;
    const int mtile = blockIdx.x >> 1;
    const int jhalf = blockIdx.x & 1;
    const int n0    = mtile * BM;
    const int wrow  = wid >> 2;         // 0..1 -> 64 m rows each
    const int wcol  = wid & 3;          // 0..3 -> 32 n cols each

    // gmem load mapping: each thread owns half a row (16 k elems)
    const int row  = t >> 1;            // 0..127
    const int koff = (t & 1) * 16;      // 0 or 16
    const uint32_t stsOff = row * (SK * 2) + koff * 2;   // byte offset in a tile array

    // two register staging sets
    float4 ra[2][4];
    uint4  rbh[2][2], rbl[2][2];

    float acc[4][4][4];
#pragma unroll
    for (int i = 0; i < 4; i++)
#pragma unroll
        for (int j = 0; j < 4; j++)
#pragma unroll
            for (int p = 0; p < 4; p++) acc[i][j][p] = 0.0f;

    // ldmatrix per-thread byte offsets (within a tile array)
    const int arow = wrow * 64 + (lane & 15);
    const int acol = (lane >> 4) * 8;
    const uint32_t aOff = arow * (SK * 2) + acol * 2;
    const int brow = wcol * 32 + (lane & 7) + ((lane >> 4) << 3);
    const int bcol = ((lane >> 3) & 1) << 3;
    const uint32_t bOff = brow * (SK * 2) + bcol * 2;

#define LOAD_AB(kt, set)                                                        \
    {                                                                           \
        const int sidx = (kt) >> 8;                                             \
        const int k0   = ((kt) & 255) * BK;                                     \
        const float* ap = supports + (size_t)sidx * NN * NN                     \
                        + (size_t)(n0 + row) * NN + k0 + koff;                  \
        ra[set][0] = *(const float4*)(ap + 0);                                  \
        ra[set][1] = *(const float4*)(ap + 4);                                  \
        ra[set][2] = *(const float4*)(ap + 8);                                  \
        ra[set][3] = *(const float4*)(ap + 12);                                 \
        const size_t boff = ((size_t)(sidx * JDIM + jhalf * 128 + row)) * NN    \
                          + k0 + koff;                                          \
        rbh[set][0] = *(const uint4*)(g_Yt_hi + boff);                          \
        rbh[set][1] = *(const uint4*)(g_Yt_hi + boff + 8);                      \
        rbl[set][0] = *(const uint4*)(g_Yt_lo + boff);                          \
        rbl[set][1] = *(const uint4*)(g_Yt_lo + boff + 8);                      \
    }

#define STS_AB(set, stageBase)                                                  \
    {                                                                           \
        char* sp = smem + (stageBase);                                          \
        uint32_t h[8], g[8];                                                    \
        _Pragma("unroll")                                                       \
        for (int q = 0; q < 4; q++) {                                           \
            float4 f = ra[set][q];                                              \
            uint32_t h01 = bf2(f.x, f.y);                                       \
            uint32_t h23 = bf2(f.z, f.w);                                       \
            float l0 = f.x - __uint_as_float(h01 << 16);                        \
            float l1 = f.y - __uint_as_float(h01 & 0xffff0000u);                \
            float l2 = f.z - __uint_as_float(h23 << 16);                        \
            float l3 = f.w - __uint_as_float(h23 & 0xffff0000u);                \
            h[2 * q] = h01; h[2 * q + 1] = h23;                                 \
            g[2 * q] = bf2(l0, l1); g[2 * q + 1] = bf2(l2, l3);                 \
        }                                                                       \
        *(uint4*)(sp + AHI_OFF + stsOff)      = make_uint4(h[0], h[1], h[2], h[3]); \
        *(uint4*)(sp + AHI_OFF + stsOff + 16) = make_uint4(h[4], h[5], h[6], h[7]); \
        *(uint4*)(sp + ALO_OFF + stsOff)      = make_uint4(g[0], g[1], g[2], g[3]); \
        *(uint4*)(sp + ALO_OFF + stsOff + 16) = make_uint4(g[4], g[5], g[6], g[7]); \
        *(uint4*)(sp + BHI_OFF + stsOff)      = rbh[set][0];                    \
        *(uint4*)(sp + BHI_OFF + stsOff + 16) = rbh[set][1];                    \
        *(uint4*)(sp + BLO_OFF + stsOff)      = rbl[set][0];                    \
        *(uint4*)(sp + BLO_OFF + stsOff + 16) = rbl[set][1];                    \
    }

    // ---- prologue: tiles 0 and 1 into regs; tile 0 into stage 0 ----
    LOAD_AB(0, 0);
    LOAD_AB(1, 1);
    STS_AB(0, 0);
    __syncthreads();

#pragma unroll 2
    for (int kt = 0; kt < KT; kt++) {
        const int st = kt & 1;

        // STS tile kt+1 into the other stage (last read in iter kt-1; safe)
        if (kt + 1 < KT) STS_AB((kt + 1) & 1, ((kt + 1) & 1) * ST_BYTES);
        // LDG tile kt+2 into the register set just freed
        if (kt + 2 < KT) LOAD_AB(kt + 2, st);

        // ---- compute from stage st (overlaps with in-flight STS/LDG) ----
        const uint32_t stage = sbase + st * ST_BYTES;
        const uint32_t aHiAddr = stage + AHI_OFF + aOff;
        const uint32_t aLoAddr = stage + ALO_OFF + aOff;
        const uint32_t bHiAddr = stage + BHI_OFF + bOff;
        const uint32_t bLoAddr = stage + BLO_OFF + bOff;

#pragma unroll
        for (int ks = 0; ks < 2; ks++) {
            uint32_t afh[4][4], afl[4][4];
#pragma unroll
            for (int mt = 0; mt < 4; mt++) {
                ldsm4(afh[mt], aHiAddr + mt * (16 * SK * 2) + ks * 32);
                ldsm4(afl[mt], aLoAddr + mt * (16 * SK * 2) + ks * 32);
            }
            uint32_t bfh[2][4], bfl[2][4];
#pragma unroll
            for (int p = 0; p < 2; p++) {
                ldsm4(bfh[p], bHiAddr + p * (16 * SK * 2) + ks * 32);
                ldsm4(bfl[p], bLoAddr + p * (16 * SK * 2) + ks * 32);
            }
#pragma unroll
            for (int mt = 0; mt < 4; mt++) {
#pragma unroll
                for (int nt = 0; nt < 4; nt++) {
                    const uint32_t* bh = &bfh[nt >> 1][(nt & 1) * 2];
                    const uint32_t* bl = &bfl[nt >> 1][(nt & 1) * 2];
                    mma_bf16(acc[mt][nt], afh[mt], bh);
                    mma_bf16(acc[mt][nt], afh[mt], bl);
                    mma_bf16(acc[mt][nt], afl[mt], bh);
                }
            }
        }
        __syncthreads();
    }

    // ---- epilogue: C frag -> out (+bias) ----
    // j = jhalf*128 + wcol*32 + (nt*8 + (lane&3)*2); b = j>>5, o = j&31
    {
        const int g    = lane >> 2;
        const int qq   = lane & 3;
        const int bidx = jhalf * 4 + wcol;
        float* obase = out + (size_t)bidx * NN * COUT;
#pragma unroll
        for (int mt = 0; mt < 4; mt++) {
            const int m = n0 + wrow * 64 + mt * 16 + g;
#pragma unroll
            for (int nt = 0; nt < 4; nt++) {
                const int o = nt * 8 + qq * 2;
                const float2 bv = *(const float2*)(bias + o);
                float2 v0, v1;
                v0.x = acc[mt][nt][0] + bv.x;
                v0.y = acc[mt][nt][1] + bv.y;
                v1.x = acc[mt][nt][2] + bv.x;
                v1.y = acc[mt][nt][3] + bv.y;
                *(float2*)(obase + (size_t)m * COUT + o)       = v0;
                *(float2*)(obase + (size_t)(m + 8) * COUT + o) = v1;
            }
        }
    }
}

// ---------------------------------------------------------------------------
extern "C" void kernel_launch(void* const* d_in, const int* in_sizes, int n_in,
                              void* d_out, int out_size) {
    const float* x        = (const float*)d_in[0];  // (8, 8192, 32)
    const float* supports = (const float*)d_in[1];  // (2, 8192, 8192)
    const float* W        = (const float*)d_in[2];  // (2, 32, 32)
    const float* bias     = (const float*)d_in[3];  // (32,)
    float* out = (float*)d_out;                     // (8, 8192, 32)
    (void)in_sizes; (void)n_in; (void)out_size;

    cudaFuncSetAttribute(graphconv_hmma_kernel,
                         cudaFuncAttributeMaxDynamicSharedMemorySize, SMEM_TOTAL);

    prep_Yt_kernel<<<dim3(64, 8, 2), 256>>>(x, W);
    graphconv_hmma_kernel<<<128, 256, SMEM_TOTAL>>>(supports, bias, out);
}

// round 10
// speedup vs baseline: 1.1732x; 1.1732x over previous
#include <cuda_runtime.h>
#include <cuda_bf16.h>
#include <cstdint>

#define NN    8192
#define SDIM  2
#define JDIM  256
#define COUT  32

#define BM 128
#define BN 128
#define BK 32
#define KT 512          // SDIM*NN / BK
#define SK 40           // padded smem row stride in bf16 elems (80B, 16B-aligned)

// Pre-split B operand: Yt[s][j][k] = Y[s][k][j], bf16 hi/lo (8.4 MB each)
__device__ __align__(256) __nv_bfloat16 g_Yt_hi[(size_t)SDIM * JDIM * NN];
__device__ __align__(256) __nv_bfloat16 g_Yt_lo[(size_t)SDIM * JDIM * NN];

// ---------------------------------------------------------------------------
// helpers
// ---------------------------------------------------------------------------
__device__ __forceinline__ uint32_t smem_u32(const void* p) {
    uint32_t a;
    asm("{ .reg .u64 t; cvta.to.shared.u64 t, %1; cvt.u32.u64 %0, t; }"
        : "=r"(a) : "l"(p));
    return a;
}

// pack two floats to bf16x2 (element0 = a, element1 = b)
__device__ __forceinline__ uint32_t bf2(float a, float b) {
    uint32_t r;
    asm("cvt.rn.bf16x2.f32 %0, %1, %2;" : "=r"(r) : "f"(b), "f"(a));
    return r;
}

__device__ __forceinline__ void ldsm4(uint32_t* r, uint32_t addr) {
    asm volatile("ldmatrix.sync.aligned.m8n8.x4.shared.b16 {%0,%1,%2,%3}, [%4];"
                 : "=r"(r[0]), "=r"(r[1]), "=r"(r[2]), "=r"(r[3]) : "r"(addr));
}

__device__ __forceinline__ void mma_bf16(float* c, const uint32_t* a, const uint32_t* b) {
    asm volatile(
        "mma.sync.aligned.m16n8k16.row.col.f32.bf16.bf16.f32 "
        "{%0,%1,%2,%3},{%4,%5,%6,%7},{%8,%9},{%0,%1,%2,%3};"
        : "+f"(c[0]), "+f"(c[1]), "+f"(c[2]), "+f"(c[3])
        : "r"(a[0]), "r"(a[1]), "r"(a[2]), "r"(a[3]), "r"(b[0]), "r"(b[1]));
}

// ---------------------------------------------------------------------------
// Kernel A: Yt_hi/lo[s][j][k] = split_bf16( sum_c x[b,k,c] * W[s,o,c] ),
//           j = b*32+o.  grid (64 kblocks, 8 b, 2 s), 256 threads.
// ---------------------------------------------------------------------------
__global__ void prep_Yt_kernel(const float* __restrict__ x,
                               const float* __restrict__ W) {
    __shared__ float Wsh[COUT][33];
    __shared__ __align__(16) float xsh[128][32];
    __shared__ __align__(16) __nv_bfloat16 yhi[COUT][128];
    __shared__ __align__(16) __nv_bfloat16 ylo[COUT][128];

    const int s  = blockIdx.z;
    const int b  = blockIdx.y;
    const int kb = blockIdx.x;
    const int t  = threadIdx.x;

    for (int i = t; i < 1024; i += 256) Wsh[i >> 5][i & 31] = W[s * 1024 + i];

    const float4* xbase = (const float4*)(x + ((size_t)b * NN + (size_t)kb * 128) * 32);
#pragma unroll
    for (int i = 0; i < 4; i++) {
        int f = t + 256 * i;
        ((float4*)&xsh[0][0])[f] = xbase[f];
    }
    __syncthreads();

    const int o = t & 31;
#pragma unroll
    for (int i = 0; i < 16; i++) {
        int ki = (t >> 5) + i * 8;
        float sum = 0.0f;
#pragma unroll
        for (int c = 0; c < 32; c++) sum += xsh[ki][c] * Wsh[o][c];
        __nv_bfloat16 h = __float2bfloat16(sum);
        float hf = __bfloat162float(h);
        __nv_bfloat16 l = __float2bfloat16(sum - hf);
        yhi[o][ki] = h;
        ylo[o][ki] = l;
    }
    __syncthreads();

    // writeback: each thread owns 16 elements = TWO uint4 (uint4 = 8 bf16)
    const int oo  = t >> 3;
    const int seg = t & 7;
    size_t base = ((size_t)(s * JDIM + b * 32 + oo)) * NN + (size_t)kb * 128 + seg * 16;
    *(uint4*)(&g_Yt_hi[base])     = *(const uint4*)(&yhi[oo][seg * 16]);
    *(uint4*)(&g_Yt_hi[base + 8]) = *(const uint4*)(&yhi[oo][seg * 16 + 8]);
    *(uint4*)(&g_Yt_lo[base])     = *(const uint4*)(&ylo[oo][seg * 16]);
    *(uint4*)(&g_Yt_lo[base + 8]) = *(const uint4*)(&ylo[oo][seg * 16 + 8]);
}

// ---------------------------------------------------------------------------
// Main GEMM via mma.sync bf16 (3-pass hi/lo split).
// Round-5 proven single-buffer structure, now with 512 threads (16 warps):
// warp grid 4x4, warp tile 32x32 -> 4 warps/SMSP for latency hiding.
// Grid: 128 CTAs = (64 m-tiles) x (2 j-halves).
// ---------------------------------------------------------------------------
__global__ __launch_bounds__(512, 1)
void graphconv_hmma_kernel(const float* __restrict__ supports,
                           const float* __restrict__ bias,
                           float* __restrict__ out) {
    __shared__ __align__(16) __nv_bfloat16 Ahi[BM][SK];
    __shared__ __align__(16) __nv_bfloat16 Alo[BM][SK];
    __shared__ __align__(16) __nv_bfloat16 Bhi[BN][SK];
    __shared__ __align__(16) __nv_bfloat16 Blo[BN][SK];

    const int t     = threadIdx.x;
    const int wid   = t >> 5;
    const int lane  = t & 31;
    const int mtile = blockIdx.x >> 1;
    const int jhalf = blockIdx.x & 1;
    const int n0    = mtile * BM;
    const int wrow  = wid >> 2;         // 0..3 -> 32 m rows each
    const int wcol  = wid & 3;          // 0..3 -> 32 n cols each

    // gmem load mapping: each thread owns a quarter row (8 k elems)
    const int row  = t >> 2;            // 0..127
    const int koff = (t & 3) * 8;       // 0,8,16,24

    float4 ra[2];                       // 8 fp32 A elems
    uint4  rbh, rbl;                    // 8 bf16 hi + 8 bf16 lo B elems

    float acc[2][4][4];
#pragma unroll
    for (int i = 0; i < 2; i++)
#pragma unroll
        for (int j = 0; j < 4; j++)
#pragma unroll
            for (int p = 0; p < 4; p++) acc[i][j][p] = 0.0f;

    // ldmatrix source addresses (per thread, fixed parts)
    const int arow = wrow * 32 + (lane & 15);
    const int acol = (lane >> 4) * 8;
    const uint32_t aHiAddr = smem_u32(&Ahi[arow][acol]);
    const uint32_t aLoAddr = smem_u32(&Alo[arow][acol]);
    const int brow = wcol * 32 + (lane & 7) + ((lane >> 4) << 3);
    const int bcol = ((lane >> 3) & 1) << 3;
    const uint32_t bHiAddr = smem_u32(&Bhi[brow][bcol]);
    const uint32_t bLoAddr = smem_u32(&Blo[brow][bcol]);

#define LOAD_A(kt)                                                              \
    {                                                                           \
        const int sidx = (kt) >> 8;                                             \
        const int k0   = ((kt) & 255) * BK;                                     \
        const float* ap = supports + (size_t)sidx * NN * NN                     \
                        + (size_t)(n0 + row) * NN + k0 + koff;                  \
        ra[0] = *(const float4*)(ap + 0);                                       \
        ra[1] = *(const float4*)(ap + 4);                                       \
    }

#define LOAD_B(kt)                                                              \
    {                                                                           \
        const int sidx = (kt) >> 8;                                             \
        const int k0   = ((kt) & 255) * BK;                                     \
        const size_t boff = ((size_t)(sidx * JDIM + jhalf * 128 + row)) * NN    \
                          + k0 + koff;                                          \
        rbh = *(const uint4*)(g_Yt_hi + boff);                                  \
        rbl = *(const uint4*)(g_Yt_lo + boff);                                  \
    }

    LOAD_A(0);
    LOAD_B(0);

    for (int kt = 0; kt < KT; kt++) {
        __syncthreads();   // previous compute done before overwriting smem

        // ---- STS: convert A to bf16 hi/lo, store B directly ----
        {
            uint32_t h01 = bf2(ra[0].x, ra[0].y);
            uint32_t h23 = bf2(ra[0].z, ra[0].w);
            uint32_t h45 = bf2(ra[1].x, ra[1].y);
            uint32_t h67 = bf2(ra[1].z, ra[1].w);
            float l0 = ra[0].x - __uint_as_float(h01 << 16);
            float l1 = ra[0].y - __uint_as_float(h01 & 0xffff0000u);
            float l2 = ra[0].z - __uint_as_float(h23 << 16);
            float l3 = ra[0].w - __uint_as_float(h23 & 0xffff0000u);
            float l4 = ra[1].x - __uint_as_float(h45 << 16);
            float l5 = ra[1].y - __uint_as_float(h45 & 0xffff0000u);
            float l6 = ra[1].z - __uint_as_float(h67 << 16);
            float l7 = ra[1].w - __uint_as_float(h67 & 0xffff0000u);
            *(uint4*)&Ahi[row][koff] = make_uint4(h01, h23, h45, h67);
            *(uint4*)&Alo[row][koff] = make_uint4(bf2(l0, l1), bf2(l2, l3),
                                                  bf2(l4, l5), bf2(l6, l7));
            *(uint4*)&Bhi[row][koff] = rbh;
            *(uint4*)&Blo[row][koff] = rbl;
        }
        __syncthreads();

        // ---- prefetch next tile into regs (overlaps with compute) ----
        if (kt + 1 < KT) {
            LOAD_A(kt + 1);
            LOAD_B(kt + 1);
        }

        // ---- compute: 2 k-steps of 16 ----
#pragma unroll
        for (int ks = 0; ks < 2; ks++) {
            uint32_t afh[2][4], afl[2][4];
#pragma unroll
            for (int mt = 0; mt < 2; mt++) {
                ldsm4(afh[mt], aHiAddr + mt * (16 * SK * 2) + ks * 32);
                ldsm4(afl[mt], aLoAddr + mt * (16 * SK * 2) + ks * 32);
            }
            uint32_t bfh[2][4], bfl[2][4];
#pragma unroll
            for (int p = 0; p < 2; p++) {
                ldsm4(bfh[p], bHiAddr + p * (16 * SK * 2) + ks * 32);
                ldsm4(bfl[p], bLoAddr + p * (16 * SK * 2) + ks * 32);
            }
#pragma unroll
            for (int mt = 0; mt < 2; mt++) {
#pragma unroll
                for (int nt = 0; nt < 4; nt++) {
                    const uint32_t* bh = &bfh[nt >> 1][(nt & 1) * 2];
                    const uint32_t* bl = &bfl[nt >> 1][(nt & 1) * 2];
                    mma_bf16(acc[mt][nt], afh[mt], bh);
                    mma_bf16(acc[mt][nt], afh[mt], bl);
                    mma_bf16(acc[mt][nt], afl[mt], bh);
                }
            }
        }
    }

    // ---- epilogue: C frag -> out (+bias) ----
    // j = jhalf*128 + wcol*32 + (nt*8 + (lane&3)*2); b = j>>5, o = j&31
    {
        const int g    = lane >> 2;
        const int qq   = lane & 3;
        const int bidx = jhalf * 4 + wcol;
        float* obase = out + (size_t)bidx * NN * COUT;
#pragma unroll
        for (int mt = 0; mt < 2; mt++) {
            const int m = n0 + wrow * 32 + mt * 16 + g;
#pragma unroll
            for (int nt = 0; nt < 4; nt++) {
                const int o = nt * 8 + qq * 2;
                const float2 bv = *(const float2*)(bias + o);
                float2 v0, v1;
                v0.x = acc[mt][nt][0] + bv.x;
                v0.y = acc[mt][nt][1] + bv.y;
                v1.x = acc[mt][nt][2] + bv.x;
                v1.y = acc[mt][nt][3] + bv.y;
                *(float2*)(obase + (size_t)m * COUT + o)       = v0;
                *(float2*)(obase + (size_t)(m + 8) * COUT + o) = v1;
            }
        }
    }
}

// ---------------------------------------------------------------------------
extern "C" void kernel_launch(void* const* d_in, const int* in_sizes, int n_in,
                              void* d_out, int out_size) {
    const float* x        = (const float*)d_in[0];  // (8, 8192, 32)
    const float* supports = (const float*)d_in[1];  // (2, 8192, 8192)
    const float* W        = (const float*)d_in[2];  // (2, 32, 32)
    const float* bias     = (const float*)d_in[3];  // (32,)
    float* out = (float*)d_out;                     // (8, 8192, 32)
    (void)in_sizes; (void)n_in; (void)out_size;

    prep_Yt_kernel<<<dim3(64, 8, 2), 256>>>(x, W);
    graphconv_hmma_kernel<<<128, 512>>>(supports, bias, out);
}